// round 3
// baseline (speedup 1.0000x reference)
#include <cuda_runtime.h>
#include <cuda_fp16.h>
#include <cstdint>

// ---------------------------------------------------------------------------
// AUGRU cell on sm_103 (base PTX only -- toolchain lowers via compute_103, so
// no tcgen05). Strategy: warp-level mma.sync.m16n8k16 (HMMA, fp16 in / fp32
// accum), persistent CTAs, weights fp16-resident in SMEM in an mma-fragment-
// permuted block layout so every fragment load is a conflict-free LDS.32 at
// (base + lane*4). u/r gate preacts accumulate x- and h-GEMM into the same
// register fragments; x_h / h_h kept separate; bias folded into accum init;
// epilogue fully in registers with tanh.approx.f32.
//
// Per CTA: 256 threads = 8 warps. M-tile = 64 rows. Warp w owns output cols
// [w*16, w*16+16) of each gate, all 64 rows:
//   acc[gate 0..3][mt 0..3][j 0..1][4 regs]  = 128 fp32 regs/thread.
// gates: 0=u, 1=r, 2=x_h, 3=h_h
// ---------------------------------------------------------------------------

#define HID 128

// SMEM layout (bytes)
#define OFF_BIAS 0          // 512 floats (u,r,xh,hh biases) = 2048 B
#define OFF_WX   2048       // 48 nt * 8 kt * 256 B = 98304
#define OFF_WH   (OFF_WX + 98304)
#define OFF_X    (OFF_WH + 98304)   // 4 mt * 8 kt * 512 B = 16384
#define OFF_H    (OFF_X + 16384)
#define SMEM_TOTAL (OFF_H + 16384)  // 229376 B = 224 KB

static __device__ __forceinline__ uint32_t h2u(__half2 h) {
    return *reinterpret_cast<uint32_t*>(&h);
}

static __device__ __forceinline__ float tanh_fast(float z) {
    float y;
    asm("tanh.approx.f32 %0, %1;" : "=f"(y) : "f"(z));
    return y;
}
static __device__ __forceinline__ float sigmoid_fast(float z) {
    return fmaf(tanh_fast(0.5f * z), 0.5f, 0.5f);
}

static __device__ __forceinline__ void mma16816(float* c, const uint32_t* a,
                                                uint32_t b0, uint32_t b1) {
    asm volatile(
        "mma.sync.aligned.m16n8k16.row.col.f32.f16.f16.f32 "
        "{%0,%1,%2,%3}, {%4,%5,%6,%7}, {%8,%9}, {%0,%1,%2,%3};"
        : "+f"(c[0]), "+f"(c[1]), "+f"(c[2]), "+f"(c[3])
        : "r"(a[0]), "r"(a[1]), "r"(a[2]), "r"(a[3]), "r"(b0), "r"(b1));
}

// Convert W fp32 [384,128] row-major -> fp16 B-fragment block layout.
// Block (kt, nt) is 16k x 8n = 256 B at (nt*8 + kt)*256:
//   first 128 B : b0 half (k = 2t, 2t+1, n = g)  at (g*4 + t)*4
//   second 128 B: b1 half (k = 2t+8, 2t+9)
static __device__ __forceinline__ void conv_weight(char* smem, uint32_t off,
                                                   const float* __restrict__ W) {
    for (int it = threadIdx.x; it < 384 * 32; it += 256) {
        int n = it >> 5;
        int k4 = (it & 31) << 2;
        float4 v = *reinterpret_cast<const float4*>(W + (size_t)n * 128 + k4);
        __half2 p0 = __floats2half2_rn(v.x, v.y);
        __half2 p1 = __floats2half2_rn(v.z, v.w);
        uint32_t base = off + (uint32_t)(((n >> 3) * 8 + (k4 >> 4)) * 256)
                      + ((k4 & 8) ? 128u : 0u);
        uint32_t o = ((uint32_t)(n & 7) << 4) + ((uint32_t)(k4 & 7) << 1);
        *reinterpret_cast<uint2*>(smem + base + o) = make_uint2(h2u(p0), h2u(p1));
    }
}

// Convert 64x128 fp32 activation rows -> fp16 A-fragment block layout.
// Block (mt, kt) is 16m x 16k = 512 B at (mt*8 + kt)*512, 4 sub-parts of 128 B:
//   sub = top + 2*hi, element (row = g + top*8, k = 2t + hi*8) at (g*4+t)*4
static __device__ __forceinline__ void conv_act(char* smem, uint32_t off,
                                                const float* __restrict__ src) {
    for (int it = threadIdx.x; it < 64 * 32; it += 256) {
        int row = it >> 5;
        int k4 = (it & 31) << 2;
        float4 v = *reinterpret_cast<const float4*>(src + (size_t)row * 128 + k4);
        __half2 p0 = __floats2half2_rn(v.x, v.y);
        __half2 p1 = __floats2half2_rn(v.z, v.w);
        uint32_t sub = (uint32_t)(((row >> 3) & 1) + (((k4 >> 3) & 1) << 1));
        uint32_t base = off + (uint32_t)(((row >> 4) * 8 + (k4 >> 4)) * 512)
                      + sub * 128u;
        uint32_t o = ((uint32_t)(row & 7) << 4) + ((uint32_t)(k4 & 7) << 1);
        *reinterpret_cast<uint2*>(smem + base + o) = make_uint2(h2u(p0), h2u(p1));
    }
}

__global__ void __launch_bounds__(256, 1) augru_kernel(
    const float* __restrict__ x, const float* __restrict__ h_prev,
    const float* __restrict__ att, const float* __restrict__ Wx,
    const float* __restrict__ bx, const float* __restrict__ Wh,
    const float* __restrict__ bh, float* __restrict__ out, int ntiles)
{
    extern __shared__ char smem[];
    const int tid = threadIdx.x;
    const int w = tid >> 5;          // warp 0..7 -> col strip [w*16, w*16+16)
    const int lane = tid & 31;
    const int g_id = lane >> 2;      // fragment group row
    const int t2 = (lane & 3) << 1;  // fragment col pair base

    // ---- one-time: combined biases + fp16 weights in fragment layout ----
    {
        float* sb = reinterpret_cast<float*>(smem + OFF_BIAS);
        if (tid < 128) {
            sb[tid]       = bx[tid] + bh[tid];               // u
            sb[128 + tid] = bx[128 + tid] + bh[128 + tid];   // r
            sb[256 + tid] = bx[256 + tid];                   // x_h
            sb[384 + tid] = bh[256 + tid];                   // h_h
        }
    }
    conv_weight(smem, OFF_WX, Wx);
    conv_weight(smem, OFF_WH, Wh);
    __syncthreads();

    const float* sb = reinterpret_cast<const float*>(smem + OFF_BIAS);

    for (int tile = blockIdx.x; tile < ntiles; tile += gridDim.x) {
        const size_t row0 = (size_t)tile * 64;

        // ---- stage x,h tiles (fp32 -> fp16 fragment layout) ----
        conv_act(smem, OFF_X, x + row0 * 128);
        conv_act(smem, OFF_H, h_prev + row0 * 128);
        __syncthreads();

        // ---- init accum with bias ----
        float acc[4][4][2][4];
        #pragma unroll
        for (int g = 0; g < 4; g++)
            #pragma unroll
            for (int j = 0; j < 2; j++) {
                float2 bb = *reinterpret_cast<const float2*>(
                    sb + g * 128 + w * 16 + j * 8 + t2);
                #pragma unroll
                for (int mt = 0; mt < 4; mt++) {
                    acc[g][mt][j][0] = bb.x; acc[g][mt][j][1] = bb.y;
                    acc[g][mt][j][2] = bb.x; acc[g][mt][j][3] = bb.y;
                }
            }

        // ---- GEMM phase 1: A = x, gates u(Wx0), r(Wx1), x_h(Wx2) ----
        #pragma unroll 1
        for (int kt = 0; kt < 8; kt++) {
            uint32_t a[4][4];
            #pragma unroll
            for (int mt = 0; mt < 4; mt++) {
                const char* ab = smem + OFF_X + (mt * 8 + kt) * 512 + lane * 4;
                a[mt][0] = *(const uint32_t*)(ab);
                a[mt][1] = *(const uint32_t*)(ab + 128);
                a[mt][2] = *(const uint32_t*)(ab + 256);
                a[mt][3] = *(const uint32_t*)(ab + 384);
            }
            #pragma unroll
            for (int j = 0; j < 2; j++)
                #pragma unroll
                for (int g = 0; g < 3; g++) {
                    int nt = g * 16 + w * 2 + j;
                    const char* bb = smem + OFF_WX + (nt * 8 + kt) * 256 + lane * 4;
                    uint32_t b0 = *(const uint32_t*)(bb);
                    uint32_t b1 = *(const uint32_t*)(bb + 128);
                    #pragma unroll
                    for (int mt = 0; mt < 4; mt++)
                        mma16816(acc[g][mt][j], a[mt], b0, b1);
                }
        }

        // ---- GEMM phase 2: A = h_prev, gates u(Wh0), r(Wh1), h_h(Wh2) ----
        #pragma unroll 1
        for (int kt = 0; kt < 8; kt++) {
            uint32_t a[4][4];
            #pragma unroll
            for (int mt = 0; mt < 4; mt++) {
                const char* ab = smem + OFF_H + (mt * 8 + kt) * 512 + lane * 4;
                a[mt][0] = *(const uint32_t*)(ab);
                a[mt][1] = *(const uint32_t*)(ab + 128);
                a[mt][2] = *(const uint32_t*)(ab + 256);
                a[mt][3] = *(const uint32_t*)(ab + 384);
            }
            #pragma unroll
            for (int j = 0; j < 2; j++)
                #pragma unroll
                for (int wg = 0; wg < 3; wg++) {
                    int g = (wg == 2) ? 3 : wg;   // Wh gate 2 -> h_h accum
                    int nt = wg * 16 + w * 2 + j;
                    const char* bb = smem + OFF_WH + (nt * 8 + kt) * 256 + lane * 4;
                    uint32_t b0 = *(const uint32_t*)(bb);
                    uint32_t b1 = *(const uint32_t*)(bb + 128);
                    #pragma unroll
                    for (int mt = 0; mt < 4; mt++)
                        mma16816(acc[g][mt][j], a[mt], b0, b1);
                }
        }

        // ---- epilogue: fully in registers ----
        #pragma unroll
        for (int mt = 0; mt < 4; mt++) {
            int r0 = (int)row0 + mt * 16 + g_id;
            int r1 = r0 + 8;
            float att0 = __ldg(att + r0);
            float att1 = __ldg(att + r1);
            #pragma unroll
            for (int j = 0; j < 2; j++) {
                int c = w * 16 + j * 8 + t2;
                const float* hp0p = h_prev + (size_t)r0 * 128 + c;
                const float* hp1p = h_prev + (size_t)r1 * 128 + c;
                float2 hp0 = *reinterpret_cast<const float2*>(hp0p);
                float2 hp1 = *reinterpret_cast<const float2*>(hp1p);

                float* uu = acc[0][mt][j];
                float* rr = acc[1][mt][j];
                float* xh = acc[2][mt][j];
                float* hh = acc[3][mt][j];

                float u0 = sigmoid_fast(uu[0]), u1 = sigmoid_fast(uu[1]);
                float u2 = sigmoid_fast(uu[2]), u3 = sigmoid_fast(uu[3]);
                float rg0 = sigmoid_fast(rr[0]), rg1 = sigmoid_fast(rr[1]);
                float rg2 = sigmoid_fast(rr[2]), rg3 = sigmoid_fast(rr[3]);
                float ht0 = tanh_fast(fmaf(rg0, hh[0], xh[0]));
                float ht1 = tanh_fast(fmaf(rg1, hh[1], xh[1]));
                float ht2 = tanh_fast(fmaf(rg2, hh[2], xh[2]));
                float ht3 = tanh_fast(fmaf(rg3, hh[3], xh[3]));

                float2 o0, o1;
                o0.x = fmaf(att0 * u0, ht0 - hp0.x, hp0.x);
                o0.y = fmaf(att0 * u1, ht1 - hp0.y, hp0.y);
                o1.x = fmaf(att1 * u2, ht2 - hp1.x, hp1.x);
                o1.y = fmaf(att1 * u3, ht3 - hp1.y, hp1.y);
                *reinterpret_cast<float2*>(out + (size_t)r0 * 128 + c) = o0;
                *reinterpret_cast<float2*>(out + (size_t)r1 * 128 + c) = o1;
            }
        }
        __syncthreads();   // compute reads done before next tile overwrites SMEM
    }
}

extern "C" void kernel_launch(void* const* d_in, const int* in_sizes, int n_in,
                              void* d_out, int out_size) {
    const float* x   = (const float*)d_in[0];
    const float* h   = (const float*)d_in[1];
    const float* att = (const float*)d_in[2];
    const float* Wx  = (const float*)d_in[3];
    const float* bx  = (const float*)d_in[4];
    const float* Wh  = (const float*)d_in[5];
    const float* bh  = (const float*)d_in[6];
    float* out = (float*)d_out;

    int B = in_sizes[2];        // att_score element count
    int ntiles = B / 64;

    cudaFuncSetAttribute(augru_kernel, cudaFuncAttributeMaxDynamicSharedMemorySize,
                         SMEM_TOTAL);

    int grid = 148;
    if (grid > ntiles) grid = ntiles;
    augru_kernel<<<grid, 256, SMEM_TOTAL>>>(x, h, att, Wx, bx, Wh, bh, out, ntiles);
}

// round 4
// speedup vs baseline: 1.1411x; 1.1411x over previous
#include <cuda_runtime.h>
#include <cuda_fp16.h>
#include <cstdint>

// ---------------------------------------------------------------------------
// AUGRU cell, sm_103 base-PTX path (no tcgen05 in compute_103).
// mma.sync.m16n8k16 fp16->fp32, persistent CTAs, fp16 weights resident in
// SMEM in an mma-fragment-permuted layout (all fragment loads = conflict-free
// LDS.32 at base + lane*4).
//
// R4 changes vs R3:
//  * 512 threads (16 warps, 4/SMSP) instead of 256 -- same total MMA work,
//    half the acc regs per thread, 2x load parallelism, better latency hiding.
//  * epilogue reads h_prev back from the fp16 h-fragment SMEM tile instead of
//    re-reading fp32 from global (saves 32MB DRAM + a latency-bound LDG burst).
//
// Warp mapping: w = mh*8 + ws; mh in {0,1} = 32-row half, ws in {0..7} =
// 16-col strip. acc[gate 0..3][mt 0..1][j 0..1][4]  (gates: u, r, x_h, h_h).
// ---------------------------------------------------------------------------

#define HID 128

// SMEM layout (bytes)
#define OFF_BIAS 0                  // 512 floats = 2048 B
#define OFF_WX   2048               // 48 nt * 8 kt * 256 B = 98304
#define OFF_WH   (OFF_WX + 98304)
#define OFF_X    (OFF_WH + 98304)   // 4 mt * 8 kt * 512 B = 16384
#define OFF_H    (OFF_X + 16384)
#define SMEM_TOTAL (OFF_H + 16384)  // 229376 B = 224 KB

static __device__ __forceinline__ uint32_t h2u(__half2 h) {
    return *reinterpret_cast<uint32_t*>(&h);
}

static __device__ __forceinline__ float tanh_fast(float z) {
    float y;
    asm("tanh.approx.f32 %0, %1;" : "=f"(y) : "f"(z));
    return y;
}
static __device__ __forceinline__ float sigmoid_fast(float z) {
    return fmaf(tanh_fast(0.5f * z), 0.5f, 0.5f);
}

static __device__ __forceinline__ void mma16816(float* c, const uint32_t* a,
                                                uint32_t b0, uint32_t b1) {
    asm volatile(
        "mma.sync.aligned.m16n8k16.row.col.f32.f16.f16.f32 "
        "{%0,%1,%2,%3}, {%4,%5,%6,%7}, {%8,%9}, {%0,%1,%2,%3};"
        : "+f"(c[0]), "+f"(c[1]), "+f"(c[2]), "+f"(c[3])
        : "r"(a[0]), "r"(a[1]), "r"(a[2]), "r"(a[3]), "r"(b0), "r"(b1));
}

// W fp32 [384,128] row-major -> fp16 B-fragment block layout.
// Block (kt, nt) = 16k x 8n = 256 B at (nt*8 + kt)*256:
//   first 128 B : b0 half (k = 2t,2t+1; n = g) at (g*4 + t)*4
//   second 128 B: b1 half (k = 2t+8,2t+9)
static __device__ __forceinline__ void conv_weight(char* smem, uint32_t off,
                                                   const float* __restrict__ W) {
    for (int it = threadIdx.x; it < 384 * 32; it += 512) {
        int n = it >> 5;
        int k4 = (it & 31) << 2;
        float4 v = *reinterpret_cast<const float4*>(W + (size_t)n * 128 + k4);
        __half2 p0 = __floats2half2_rn(v.x, v.y);
        __half2 p1 = __floats2half2_rn(v.z, v.w);
        uint32_t base = off + (uint32_t)(((n >> 3) * 8 + (k4 >> 4)) * 256)
                      + ((k4 & 8) ? 128u : 0u);
        uint32_t o = ((uint32_t)(n & 7) << 4) + ((uint32_t)(k4 & 7) << 1);
        *reinterpret_cast<uint2*>(smem + base + o) = make_uint2(h2u(p0), h2u(p1));
    }
}

// 64x128 fp32 activation rows -> fp16 A-fragment block layout.
// Block (mt, kt) = 16m x 16k = 512 B at (mt*8 + kt)*512, 4 subparts of 128 B:
//   sub = top + 2*hi : (row = g + top*8, k = 2t + hi*8) at (g*4 + t)*4
static __device__ __forceinline__ void conv_act(char* smem, uint32_t off,
                                                const float* __restrict__ src) {
    #pragma unroll
    for (int ii = 0; ii < 4; ii++) {
        int it = ii * 512 + threadIdx.x;
        int row = it >> 5;
        int k4 = (it & 31) << 2;
        float4 v = *reinterpret_cast<const float4*>(src + (size_t)row * 128 + k4);
        __half2 p0 = __floats2half2_rn(v.x, v.y);
        __half2 p1 = __floats2half2_rn(v.z, v.w);
        uint32_t sub = (uint32_t)(((row >> 3) & 1) + (((k4 >> 3) & 1) << 1));
        uint32_t base = off + (uint32_t)(((row >> 4) * 8 + (k4 >> 4)) * 512)
                      + sub * 128u;
        uint32_t o = ((uint32_t)(row & 7) << 4) + ((uint32_t)(k4 & 7) << 1);
        *reinterpret_cast<uint2*>(smem + base + o) = make_uint2(h2u(p0), h2u(p1));
    }
}

__global__ void __launch_bounds__(512, 1) augru_kernel(
    const float* __restrict__ x, const float* __restrict__ h_prev,
    const float* __restrict__ att, const float* __restrict__ Wx,
    const float* __restrict__ bx, const float* __restrict__ Wh,
    const float* __restrict__ bh, float* __restrict__ out, int ntiles)
{
    extern __shared__ char smem[];
    const int tid = threadIdx.x;
    const int w = tid >> 5;
    const int mh = w >> 3;           // 32-row half: mt tiles {2mh, 2mh+1}
    const int ws = w & 7;            // 16-col strip [ws*16, ws*16+16)
    const int lane = tid & 31;
    const int g_id = lane >> 2;
    const int t2 = (lane & 3) << 1;

    // ---- one-time: combined biases + fp16 weights in fragment layout ----
    {
        float* sb = reinterpret_cast<float*>(smem + OFF_BIAS);
        if (tid < 128) {
            sb[tid]       = bx[tid] + bh[tid];               // u
            sb[128 + tid] = bx[128 + tid] + bh[128 + tid];   // r
            sb[256 + tid] = bx[256 + tid];                   // x_h
            sb[384 + tid] = bh[256 + tid];                   // h_h
        }
    }
    conv_weight(smem, OFF_WX, Wx);
    conv_weight(smem, OFF_WH, Wh);
    __syncthreads();

    const float* sb = reinterpret_cast<const float*>(smem + OFF_BIAS);

    for (int tile = blockIdx.x; tile < ntiles; tile += gridDim.x) {
        const size_t row0 = (size_t)tile * 64;

        // ---- stage x,h tiles (fp32 -> fp16 fragment layout) ----
        conv_act(smem, OFF_X, x + row0 * 128);
        conv_act(smem, OFF_H, h_prev + row0 * 128);
        __syncthreads();

        // ---- init accum with bias ----
        float acc[4][2][2][4];
        #pragma unroll
        for (int g = 0; g < 4; g++)
            #pragma unroll
            for (int j = 0; j < 2; j++) {
                float2 bb = *reinterpret_cast<const float2*>(
                    sb + g * 128 + ws * 16 + j * 8 + t2);
                #pragma unroll
                for (int mt = 0; mt < 2; mt++) {
                    acc[g][mt][j][0] = bb.x; acc[g][mt][j][1] = bb.y;
                    acc[g][mt][j][2] = bb.x; acc[g][mt][j][3] = bb.y;
                }
            }

        // ---- GEMM phase 1: A = x, gates u(Wx0), r(Wx1), x_h(Wx2) ----
        #pragma unroll 1
        for (int kt = 0; kt < 8; kt++) {
            uint32_t a[2][4];
            #pragma unroll
            for (int mt = 0; mt < 2; mt++) {
                const char* ab = smem + OFF_X + ((mh * 2 + mt) * 8 + kt) * 512 + lane * 4;
                a[mt][0] = *(const uint32_t*)(ab);
                a[mt][1] = *(const uint32_t*)(ab + 128);
                a[mt][2] = *(const uint32_t*)(ab + 256);
                a[mt][3] = *(const uint32_t*)(ab + 384);
            }
            #pragma unroll
            for (int j = 0; j < 2; j++)
                #pragma unroll
                for (int g = 0; g < 3; g++) {
                    int nt = g * 16 + ws * 2 + j;
                    const char* bb = smem + OFF_WX + (nt * 8 + kt) * 256 + lane * 4;
                    uint32_t b0 = *(const uint32_t*)(bb);
                    uint32_t b1 = *(const uint32_t*)(bb + 128);
                    #pragma unroll
                    for (int mt = 0; mt < 2; mt++)
                        mma16816(acc[g][mt][j], a[mt], b0, b1);
                }
        }

        // ---- GEMM phase 2: A = h_prev, gates u(Wh0), r(Wh1), h_h(Wh2) ----
        #pragma unroll 1
        for (int kt = 0; kt < 8; kt++) {
            uint32_t a[2][4];
            #pragma unroll
            for (int mt = 0; mt < 2; mt++) {
                const char* ab = smem + OFF_H + ((mh * 2 + mt) * 8 + kt) * 512 + lane * 4;
                a[mt][0] = *(const uint32_t*)(ab);
                a[mt][1] = *(const uint32_t*)(ab + 128);
                a[mt][2] = *(const uint32_t*)(ab + 256);
                a[mt][3] = *(const uint32_t*)(ab + 384);
            }
            #pragma unroll
            for (int j = 0; j < 2; j++)
                #pragma unroll
                for (int wg = 0; wg < 3; wg++) {
                    int g = (wg == 2) ? 3 : wg;   // Wh gate 2 -> h_h accum
                    int nt = wg * 16 + ws * 2 + j;
                    const char* bb = smem + OFF_WH + (nt * 8 + kt) * 256 + lane * 4;
                    uint32_t b0 = *(const uint32_t*)(bb);
                    uint32_t b1 = *(const uint32_t*)(bb + 128);
                    #pragma unroll
                    for (int mt = 0; mt < 2; mt++)
                        mma16816(acc[g][mt][j], a[mt], b0, b1);
                }
        }

        // ---- epilogue: h_prev re-read from fp16 h-fragment SMEM ----
        #pragma unroll
        for (int mt = 0; mt < 2; mt++) {
            int mtg = mh * 2 + mt;
            int r0 = (int)row0 + mtg * 16 + g_id;
            int r1 = r0 + 8;
            float att0 = __ldg(att + r0);
            float att1 = __ldg(att + r1);
            #pragma unroll
            for (int j = 0; j < 2; j++) {
                int c = ws * 16 + j * 8 + t2;
                // h fragment: block (mtg, kt=ws), sub = top + 2*j, offset g*16+t2*2
                const char* hb = smem + OFF_H + (mtg * 8 + ws) * 512
                               + 2 * j * 128 + g_id * 16 + t2 * 2;
                float2 hp0 = __half22float2(*(const __half2*)(hb));
                float2 hp1 = __half22float2(*(const __half2*)(hb + 128));

                float* uu = acc[0][mt][j];
                float* rr = acc[1][mt][j];
                float* xh = acc[2][mt][j];
                float* hh = acc[3][mt][j];

                float u0 = sigmoid_fast(uu[0]), u1 = sigmoid_fast(uu[1]);
                float u2 = sigmoid_fast(uu[2]), u3 = sigmoid_fast(uu[3]);
                float rg0 = sigmoid_fast(rr[0]), rg1 = sigmoid_fast(rr[1]);
                float rg2 = sigmoid_fast(rr[2]), rg3 = sigmoid_fast(rr[3]);
                float ht0 = tanh_fast(fmaf(rg0, hh[0], xh[0]));
                float ht1 = tanh_fast(fmaf(rg1, hh[1], xh[1]));
                float ht2 = tanh_fast(fmaf(rg2, hh[2], xh[2]));
                float ht3 = tanh_fast(fmaf(rg3, hh[3], xh[3]));

                float2 o0, o1;
                o0.x = fmaf(att0 * u0, ht0 - hp0.x, hp0.x);
                o0.y = fmaf(att0 * u1, ht1 - hp0.y, hp0.y);
                o1.x = fmaf(att1 * u2, ht2 - hp1.x, hp1.x);
                o1.y = fmaf(att1 * u3, ht3 - hp1.y, hp1.y);
                *reinterpret_cast<float2*>(out + (size_t)r0 * 128 + c) = o0;
                *reinterpret_cast<float2*>(out + (size_t)r1 * 128 + c) = o1;
            }
        }
        __syncthreads();   // SMEM reads done before next tile overwrites
    }
}

extern "C" void kernel_launch(void* const* d_in, const int* in_sizes, int n_in,
                              void* d_out, int out_size) {
    const float* x   = (const float*)d_in[0];
    const float* h   = (const float*)d_in[1];
    const float* att = (const float*)d_in[2];
    const float* Wx  = (const float*)d_in[3];
    const float* bx  = (const float*)d_in[4];
    const float* Wh  = (const float*)d_in[5];
    const float* bh  = (const float*)d_in[6];
    float* out = (float*)d_out;

    int B = in_sizes[2];        // att_score element count
    int ntiles = B / 64;

    cudaFuncSetAttribute(augru_kernel, cudaFuncAttributeMaxDynamicSharedMemorySize,
                         SMEM_TOTAL);

    int grid = 148;
    if (grid > ntiles) grid = ntiles;
    augru_kernel<<<grid, 512, SMEM_TOTAL>>>(x, h, att, Wx, bx, Wh, bh, out, ntiles);
}